// round 14
// baseline (speedup 1.0000x reference)
#include <cuda_runtime.h>
#include <stdint.h>

#define BB 16
#define AA 12
#define HH 64
#define WW 64
#define GG 64
#define NN (AA*HH*WW)        /* 49152 anchors per batch */
#define TOT (BB*NN)          /* 786432 */
#define NBUCK 1024
#define SENT 0xFFFFFFFFu
#define SLOTS 128

// ---------------- scratch (static __device__, no allocation) ----------------
// INVARIANT: g_hist, g_pos, g_neg are zero at every kernel_launch entry
// (zero at module load; finish_kernel re-zeroes them each call; g_done
// self-wraps via atomicInc). g_list/g_ubuf are fully overwritten before read.
__device__ unsigned g_ubuf[TOT];                       // fallback store of u
__device__ unsigned g_hist[BB*NBUCK];                  // counts (u>>13)
__device__ unsigned long long g_list[(size_t)BB*NBUCK*SLOTS]; // (u<<32)|idx
__device__ unsigned g_pos, g_neg;
__device__ unsigned g_done;                            // wraps 0..15

// ------- Threefry-2x32-20, key=(0,42), PARTITIONABLE layout -----------------
__device__ __forceinline__ unsigned threefry_bits(unsigned i) {
    unsigned x0 = 0u, x1 = i;
    const unsigned k0 = 0u, k1 = 42u, k2 = 0x1BD11BDAu ^ 0u ^ 42u;
    x0 += k0; x1 += k1;
#define TFR(r) { x0 += x1; x1 = __funnelshift_l(x1, x1, (r)); x1 ^= x0; }
    TFR(13) TFR(15) TFR(26) TFR(6)   x0 += k1; x1 += k2 + 1u;
    TFR(17) TFR(29) TFR(16) TFR(24)  x0 += k2; x1 += k0 + 2u;
    TFR(13) TFR(15) TFR(26) TFR(6)   x0 += k0; x1 += k1 + 3u;
    TFR(17) TFR(29) TFR(16) TFR(24)  x0 += k1; x1 += k2 + 4u;
    TFR(13) TFR(15) TFR(26) TFR(6)   x0 += k2; x1 += k0 + 5u;
#undef TFR
    return x0 ^ x1;
}

// ---------------- kernel 1: IoU / labels / targets / PRNG / lists -----------
// (identical to R12 best) Block = (jt, a, b): 64 rows x 8 columns; warp w owns
// column j = jt*8 + w; lane l owns rows l and l+32. Separable IoU + compacted
// g-list; division-free guard with exact __fdiv_rn fallback => bit-identical.
// Label-0 written as -1 tentatively; finish pass flips kept ones back to 0.
__global__ void __launch_bounds__(256) main_kernel(
        const float* __restrict__ gt,       // (B,G,4)
        const float* __restrict__ anchors,  // (N,4)
        float* __restrict__ out)            // (B,N,5)
{
    __shared__ float4 s_gb[GG];          // (gx0, gy0, gx1, gy1)
    __shared__ float4 s_g0[GG];          // raw batch-0 gt boxes (targets quirk)
    __shared__ float  s_ga[GG];
    __shared__ float  s_u0[GG];          // aarea + ga
    __shared__ float  s_ax0[8], s_ax1[8];
    __shared__ float  s_ay0[HH], s_ay1[HH];
    __shared__ float  s_iw[8*GG];        // [jl][g]
    __shared__ float2 s_ih2[GG*32];      // [g][l] -> (ih row l, ih row l+32)
    __shared__ unsigned char s_lg[8*GG]; // compacted g indices per column
    __shared__ int    s_nl[8], s_fza[8]; // list length, first iw==0 g
    __shared__ float  s_out[HH*8*5];     // staged output (2560 floats)
    __shared__ unsigned s_ub[HH*8];      // staged u
    __shared__ unsigned s_p, s_n;

    const int b  = blockIdx.z;
    const int a  = blockIdx.y;
    const int jt = blockIdx.x;
    const int j0 = jt * 8;
    const int t  = threadIdx.x;
    const int w  = t >> 5;               // local column
    const int l  = t & 31;

    const float4* anc4 = (const float4*)anchors;

    // ---- phase 1: stage ----
    if (t == 0) { s_p = 0u; s_n = 0u; }
    if (t < GG) {
        const float4 gp = *(const float4*)(gt + ((size_t)b*GG + t)*4);
        s_gb[t] = make_float4(gp.x, gp.y,
                              __fadd_rn(gp.x, gp.z), __fadd_rn(gp.y, gp.w));
        s_ga[t] = __fmul_rn(gp.z, gp.w);
    } else if (t < 2*GG) {
        s_g0[t - GG] = *(const float4*)(gt + (size_t)(t - GG)*4);   // batch 0
    } else if (t < 136) {
        int k = t - 128;
        float4 v = anc4[a*HH*WW + j0 + k];      // x0(j): i-invariant
        s_ax0[k] = v.x; s_ax1[k] = __fadd_rn(v.x, v.z);
    } else if (t >= 192) {
        int i = t - 192;
        float4 v = anc4[(a*HH + i)*WW];         // y0(i): j-invariant
        s_ay0[i] = v.y; s_ay1[i] = __fadd_rn(v.y, v.w);
    }
    const float4 A0 = anc4[a*HH*WW];            // w,h constant per a
    const float aw = A0.z, ah = A0.w;
    const float aarea = __fmul_rn(aw, ah);
    __syncthreads();

    // ---- phase 2: separable precompute ----
    if (t < GG) s_u0[t] = __fadd_rn(aarea, s_ga[t]);
#pragma unroll
    for (int k = 0; k < 2; ++k) {               // iw: 512 entries
        int idx = t + k*256;
        int g = idx & 63, jl = idx >> 6;
        const float4 gb = s_gb[g];
        s_iw[jl*64 + g] = fmaxf(0.f, __fsub_rn(fminf(s_ax1[jl], gb.z),
                                               fmaxf(s_ax0[jl], gb.x)));
    }
#pragma unroll
    for (int k = 0; k < 8; ++k) {               // ih2: 2048 float2 entries
        int idx = t + k*256;
        int g = idx >> 5, ll = idx & 31;
        const float4 gb = s_gb[g];
        float v0 = fmaxf(0.f, __fsub_rn(fminf(s_ay1[ll],    gb.w), fmaxf(s_ay0[ll],    gb.y)));
        float v1 = fmaxf(0.f, __fsub_rn(fminf(s_ay1[ll+32], gb.w), fmaxf(s_ay0[ll+32], gb.y)));
        s_ih2[g*32 + ll] = make_float2(v0, v1);
    }
    __syncthreads();

    // ---- compaction: list of g with iw>0 for this warp's column ----
    {
        float iwA = s_iw[w*64 + l];
        float iwB = s_iw[w*64 + 32 + l];
        unsigned b0 = __ballot_sync(0xFFFFFFFFu, iwA > 0.f);
        unsigned b1 = __ballot_sync(0xFFFFFFFFu, iwB > 0.f);
        int cnt0 = __popc(b0);
        if (b0 & (1u << l)) s_lg[w*64 + __popc(b0 & ((1u<<l)-1u))] = (unsigned char)l;
        if (b1 & (1u << l)) s_lg[w*64 + cnt0 + __popc(b1 & ((1u<<l)-1u))] = (unsigned char)(l + 32);
        if (l == 0) {
            s_nl[w] = cnt0 + __popc(b1);
            unsigned nb0 = ~b0, nb1 = ~b1;
            int fz = 64;
            if (nb0)      fz = __ffs(nb0) - 1;
            else if (nb1) fz = 32 + __ffs(nb1) - 1;
            s_fza[w] = fz;
        }
    }
    __syncwarp();

    // ---- main loop over compacted list (ascending g) ----
    const int nl = s_nl[w];
    float best0 = -1.f, bsl0 = -1.f; int bg0 = 0, fz0 = 64;
    float best1 = -1.f, bsl1 = -1.f; int bg1 = 0, fz1 = 64;

    for (int s = 0; s < nl; ++s) {
        const int   g  = (int)s_lg[w*64 + s];
        const float iw = s_iw[w*64 + g];
        const float2 ih = s_ih2[g*32 + l];
        const float u0 = s_u0[g];
        {   // row l
            float inter = __fmul_rn(iw, ih.x);
            if (inter == 0.f) { if (fz0 == 64) fz0 = g; }
            else {
                float uni = __fsub_rn(u0, inter);
                if (__fmaf_rn(-bsl0, uni, inter) >= 0.f) {   // conservative, rare
                    float ov = __fdiv_rn(inter, uni);
                    if (ov == 0.f) ov = 1e-10f;
                    if (ov > best0) {
                        best0 = ov; bg0 = g;
                        bsl0 = __fmul_rn(best0, 0.99999952f); // 1 - 2^-21
                    }
                }
            }
        }
        {   // row l+32
            float inter = __fmul_rn(iw, ih.y);
            if (inter == 0.f) { if (fz1 == 64) fz1 = g; }
            else {
                float uni = __fsub_rn(u0, inter);
                if (__fmaf_rn(-bsl1, uni, inter) >= 0.f) {
                    float ov = __fdiv_rn(inter, uni);
                    if (ov == 0.f) ov = 1e-10f;
                    if (ov > best1) {
                        best1 = ov; bg1 = g;
                        bsl1 = __fmul_rn(best1, 0.99999952f);
                    }
                }
            }
        }
    }
    // merge zero-candidates (value 1e-10 at first zero-inter index)
    {
        int fz = min(s_fza[w], fz0);
        if (fz < 64) {
            if (best0 < 1e-10f)                     { best0 = 1e-10f; bg0 = fz; }
            else if (best0 == 1e-10f && fz < bg0)   bg0 = fz;
        }
        fz = min(s_fza[w], fz1);
        if (fz < 64) {
            if (best1 < 1e-10f)                     { best1 = 1e-10f; bg1 = fz; }
            else if (best1 == 1e-10f && fz < bg1)   bg1 = fz;
        }
    }

    // ---- epilogue ----
    const float L = 63.0f;
    const float x0 = s_ax0[w];
    const bool keep_x = (x0 >= 0.f) && (aw >= 0.f) && (ah >= 0.f) &&
                        (x0 <= L) && (__fsub_rn(s_ax1[w], 1.0f) <= L);
    int myp = 0, myn = 0;

#pragma unroll
    for (int rr = 0; rr < 2; ++rr) {
        const int   i    = rr ? (l + 32) : l;
        const float best = rr ? best1 : best0;
        const int   bg   = rr ? bg1 : bg0;
        const float y0 = s_ay0[i];
        const bool keep = keep_x && (y0 >= 0.f) && (y0 <= L) &&
                          (__fsub_rn(s_ay1[i], 1.0f) <= L);

        float label = -1.0f; bool lab0 = false;
        if (keep) {
            if (best >= 0.7f)       label = 1.0f;
            else if (best <= 0.3f)  lab0 = true;   // tentative -1
            myp += (best > 0.7f);
            myn += (best < 0.3f);
        }

        float* so = s_out + (i*8 + w)*5;
        so[0] = label;
        if (keep) {
            const float4 g0 = s_g0[bg];
            so[1] = __fsub_rn(x0, __fmul_rn(g0.x, 0.0625f));
            so[2] = __fsub_rn(y0, __fmul_rn(g0.y, 0.0625f));
            so[3] = __fsub_rn(aw, __fmul_rn(g0.z, 0.0625f));
            so[4] = __fsub_rn(ah, __fmul_rn(g0.w, 0.0625f));
        } else {
            so[1] = 0.f; so[2] = 0.f; so[3] = 0.f; so[4] = 0.f;
        }

        const int n = (a*HH + i)*WW + (j0 + w);
        unsigned u = SENT;
        if (lab0) {
            u = threefry_bits((unsigned)(b*NN + n)) >> 9;
            int bucket = (int)(u >> 13);
            unsigned slot = atomicAdd(&g_hist[b*NBUCK + bucket], 1u);
            if (slot < SLOTS)
                g_list[((size_t)(b*NBUCK + bucket))*SLOTS + slot] =
                    ((unsigned long long)u << 32) | (unsigned)n;
        }
        s_ub[i*8 + w] = u;
    }

    for (int o = 16; o > 0; o >>= 1) {
        myp += __shfl_down_sync(0xFFFFFFFFu, myp, o);
        myn += __shfl_down_sync(0xFFFFFFFFu, myn, o);
    }
    if (l == 0) {
        if (myp) atomicAdd(&s_p, (unsigned)myp);
        if (myn) atomicAdd(&s_n, (unsigned)myn);
    }
    __syncthreads();
    if (t == 0) {
        if (s_p) atomicAdd(&g_pos, s_p);
        if (s_n) atomicAdd(&g_neg, s_n);
    }

    // ---- staged writes ----
    const float4* so4 = (const float4*)s_out;
    float4* o4 = (float4*)out;
    const size_t obase = (size_t)(b*AA + a) * 5120;   // HH*WW*5/4
#pragma unroll
    for (int k = 0; k < 3; ++k) {
        int f = t + k*256;
        if (f < 640) {
            int i = f / 10, p = f % 10;
            o4[obase + (size_t)i*80 + jt*10 + p] = so4[f];
        }
    }
    if (t < 128) {
        int i = t >> 1, part = t & 1;
        const uint4* su4 = (const uint4*)s_ub;
        uint4* u4 = (uint4*)g_ubuf;
        u4[((size_t)b*NN + a*HH*WW)/4 + (size_t)i*16 + jt*2 + part] = su4[t];
    }
}

// ---------------- kernel 2: fused scan + restore + state-clean --------------
// 16 blocks (one per row) x 1024 threads. Each block:
//  1. reads pos/neg via shared (load->shared-store->barrier closes the
//     read-before-zero race); 16th block (self-wrapping done-counter)
//     zeroes g_pos/g_neg for the next replay.
//  2. stages its hist row to shared, zeroes the global row (self-clean).
//  3. block-scans descending buckets -> T, S; ovf check.
//  4. restores kept negatives: warp-strided buckets above T from shared
//     counts; fine-ranks boundary bucket T; fallbacks preserved.
__global__ void __launch_bounds__(1024) finish_kernel(float* __restrict__ out) {
    const int b = blockIdx.x;
    const int t = threadIdx.x;

    __shared__ unsigned sh_cnt[NBUCK];   // counts by bucket
    __shared__ unsigned sh[1024];        // scan workspace
    __shared__ unsigned s_pn[2];
    __shared__ int s_T, s_ovf;
    __shared__ unsigned s_S;
    __shared__ unsigned s_u[SLOTS], s_i[SLOTS];

    if (t == 0) {
        s_pn[0] = g_pos; s_pn[1] = g_neg;   // loads complete before the
        s_T = -1; s_ovf = 0;                 // dependent shared stores do
    }
    unsigned* hrow = g_hist + b*NBUCK;
    const unsigned cnt = hrow[t];            // own bucket t
    sh_cnt[t] = cnt;
    __syncthreads();                         // pos/neg + counts staged
    hrow[t] = 0u;                            // self-clean for next replay
    if (t == 0) {
        unsigned old = atomicInc(&g_done, 15u);   // wraps 15 -> 0
        if (old == 15u) { g_pos = 0u; g_neg = 0u; }  // all 16 blocks have read
    }

    const unsigned pos = s_pn[0], negc = s_pn[1];
    const unsigned cutoff = (unsigned)max(1, 3 * (int)pos);
    const unsigned* row = g_ubuf + (size_t)b*NN;

    if (negc <= cutoff) {
        // no disable: restore ALL label-0 (u != SENT)
        const uint4* r4 = (const uint4*)row;
#pragma unroll
        for (int k = 0; k < 12; ++k) {       // 12288 uint4 / 1024 threads
            int f = t + k*1024;
            uint4 u4 = r4[f];
            int j = f*4;
            if (u4.x != SENT) out[((size_t)b*NN + j+0)*5] = 0.0f;
            if (u4.y != SENT) out[((size_t)b*NN + j+1)*5] = 0.0f;
            if (u4.z != SENT) out[((size_t)b*NN + j+2)*5] = 0.0f;
            if (u4.w != SENT) out[((size_t)b*NN + j+3)*5] = 0.0f;
        }
        return;
    }

    // ---- block scan over descending buckets: thread t covers hi = 1023-t ----
    const int hi = (NBUCK - 1) - t;
    const unsigned v = sh_cnt[hi];
    sh[t] = v;
    __syncthreads();
    for (int o = 1; o < 1024; o <<= 1) {
        unsigned add = (t >= o) ? sh[t - o] : 0u;
        __syncthreads();
        sh[t] += add;
        __syncthreads();
    }
    const unsigned incl = sh[t];
    const unsigned excl = incl - v;
    if (excl < cutoff && incl >= cutoff) { s_T = hi; s_S = excl; }  // unique
    __syncthreads();
    const int T = s_T;
    const unsigned S = s_S;
    // T always found: sum(hist) = #label0 >= negc > cutoff.

    if (hi >= T && v > SLOTS) s_ovf = 1;     // benign race
    __syncthreads();

    if (!s_ovf) {
        // warp-strided buckets above T; counts from shared (no global chain)
        const int W = t >> 5, l = t & 31;    // 32 warps
        for (int q = T + 1 + W; q < NBUCK; q += 32) {
            const unsigned c = sh_cnt[q];
            const unsigned long long* lst = g_list + ((size_t)(b*NBUCK + q))*SLOTS;
            for (unsigned e = l; e < c; e += 32) {
                unsigned idx = (unsigned)(lst[e] & 0xFFFFFFFFu);
                out[((size_t)b*NN + idx)*5] = 0.0f;
            }
        }
        // boundary bucket T: exact rank (cT <= SLOTS since no overflow)
        const unsigned cT = sh_cnt[T];
        const unsigned long long* lst = g_list + ((size_t)(b*NBUCK + T))*SLOTS;
        if (t < cT) {
            unsigned long long p = lst[t];
            s_u[t] = (unsigned)(p >> 32);
            s_i[t] = (unsigned)(p & 0xFFFFFFFFu);
        }
        __syncthreads();
        if (t < cT) {
            unsigned ua = s_u[t], ia = s_i[t];
            unsigned c2 = S;
            for (unsigned k = 0; k < cT; ++k) {
                unsigned ub = s_u[k];
                if (ub > ua || (ub == ua && s_i[k] < ia)) c2++;
            }
            if (c2 < cutoff) out[((size_t)b*NN + ia)*5] = 0.0f;   // kept
        }
    } else {
        // overflow fallback: full-row scan via g_ubuf
        for (int j = t; j < NN; j += 1024) {
            unsigned u = row[j];
            if (u != SENT && (int)(u >> 13) > T)
                out[((size_t)b*NN + j)*5] = 0.0f;
        }
        for (int a = t; a < NN; a += 1024) {
            unsigned ua = row[a];
            if (ua == SENT || (int)(ua >> 13) != T) continue;
            unsigned c2 = S;
            for (int jx = 0; jx < NN; ++jx) {
                unsigned uj = row[jx];
                if (uj != SENT && (int)(uj >> 13) == T &&
                    (uj > ua || (uj == ua && jx < a))) c2++;
            }
            if (c2 < cutoff) out[((size_t)b*NN + a)*5] = 0.0f;
        }
    }
}

// ---------------- launch ----------------------------------------------------
extern "C" void kernel_launch(void* const* d_in, const int* in_sizes, int n_in,
                              void* d_out, int out_size) {
    const float* gt      = (const float*)d_in[1];
    const float* anchors = (const float*)d_in[2];
    for (int k = 0; k < n_in; ++k) {
        if (in_sizes[k] == BB*GG*4) gt      = (const float*)d_in[k];
        if (in_sizes[k] == NN*4)    anchors = (const float*)d_in[k];
    }
    float* out = (float*)d_out;

    dim3 mgrid(8, AA, BB);                 // 8 j-tiles x 12 a x 16 b = 1536
    main_kernel<<<mgrid, 256>>>(gt, anchors, out);
    finish_kernel<<<BB, 1024>>>(out);
}

// round 16
// speedup vs baseline: 1.0444x; 1.0444x over previous
#include <cuda_runtime.h>
#include <stdint.h>

#define BB 16
#define AA 12
#define HH 64
#define WW 64
#define GG 64
#define NN (AA*HH*WW)        /* 49152 anchors per batch */
#define TOT (BB*NN)          /* 786432 */
#define NBUCK 1024
#define SENT 0xFFFFFFFFu
#define SLOTS 128

// ---------------- scratch (static __device__, no allocation) ----------------
// INVARIANT: g_hist, g_pos, g_neg are zero at every kernel_launch entry
// (zero at module load; finish_kernel re-zeroes them each call; g_done
// self-wraps via atomicInc). g_list/g_ubuf are fully overwritten before read.
__device__ unsigned g_ubuf[TOT];                       // fallback store of u
__device__ unsigned g_hist[BB*NBUCK];                  // counts (u>>13)
__device__ unsigned long long g_list[(size_t)BB*NBUCK*SLOTS]; // (u<<32)|idx
__device__ unsigned g_pos, g_neg;
__device__ unsigned g_done;                            // wraps 0..15

// ------- Threefry-2x32-20, key=(0,42), PARTITIONABLE layout -----------------
__device__ __forceinline__ unsigned threefry_bits(unsigned i) {
    unsigned x0 = 0u, x1 = i;
    const unsigned k0 = 0u, k1 = 42u, k2 = 0x1BD11BDAu ^ 0u ^ 42u;
    x0 += k0; x1 += k1;
#define TFR(r) { x0 += x1; x1 = __funnelshift_l(x1, x1, (r)); x1 ^= x0; }
    TFR(13) TFR(15) TFR(26) TFR(6)   x0 += k1; x1 += k2 + 1u;
    TFR(17) TFR(29) TFR(16) TFR(24)  x0 += k2; x1 += k0 + 2u;
    TFR(13) TFR(15) TFR(26) TFR(6)   x0 += k0; x1 += k1 + 3u;
    TFR(17) TFR(29) TFR(16) TFR(24)  x0 += k1; x1 += k2 + 4u;
    TFR(13) TFR(15) TFR(26) TFR(6)   x0 += k2; x1 += k0 + 5u;
#undef TFR
    return x0 ^ x1;
}

// ---------------- kernel 1: IoU / labels / targets / PRNG / lists -----------
// (identical to R12/R14 best) Block = (jt, a, b): 64 rows x 8 columns; warp w
// owns column j = jt*8 + w; lane l owns rows l and l+32. Separable IoU +
// compacted g-list; division-free guard with exact __fdiv_rn fallback =>
// bit-identical. Label-0 written as -1 tentatively; finish restores kept ones.
__global__ void __launch_bounds__(256) main_kernel(
        const float* __restrict__ gt,       // (B,G,4)
        const float* __restrict__ anchors,  // (N,4)
        float* __restrict__ out)            // (B,N,5)
{
    __shared__ float4 s_gb[GG];          // (gx0, gy0, gx1, gy1)
    __shared__ float4 s_g0[GG];          // raw batch-0 gt boxes (targets quirk)
    __shared__ float  s_ga[GG];
    __shared__ float  s_u0[GG];          // aarea + ga
    __shared__ float  s_ax0[8], s_ax1[8];
    __shared__ float  s_ay0[HH], s_ay1[HH];
    __shared__ float  s_iw[8*GG];        // [jl][g]
    __shared__ float2 s_ih2[GG*32];      // [g][l] -> (ih row l, ih row l+32)
    __shared__ unsigned char s_lg[8*GG]; // compacted g indices per column
    __shared__ int    s_nl[8], s_fza[8]; // list length, first iw==0 g
    __shared__ float  s_out[HH*8*5];     // staged output (2560 floats)
    __shared__ unsigned s_ub[HH*8];      // staged u
    __shared__ unsigned s_p, s_n;

    const int b  = blockIdx.z;
    const int a  = blockIdx.y;
    const int jt = blockIdx.x;
    const int j0 = jt * 8;
    const int t  = threadIdx.x;
    const int w  = t >> 5;               // local column
    const int l  = t & 31;

    const float4* anc4 = (const float4*)anchors;

    // ---- phase 1: stage ----
    if (t == 0) { s_p = 0u; s_n = 0u; }
    if (t < GG) {
        const float4 gp = *(const float4*)(gt + ((size_t)b*GG + t)*4);
        s_gb[t] = make_float4(gp.x, gp.y,
                              __fadd_rn(gp.x, gp.z), __fadd_rn(gp.y, gp.w));
        s_ga[t] = __fmul_rn(gp.z, gp.w);
    } else if (t < 2*GG) {
        s_g0[t - GG] = *(const float4*)(gt + (size_t)(t - GG)*4);   // batch 0
    } else if (t < 136) {
        int k = t - 128;
        float4 v = anc4[a*HH*WW + j0 + k];      // x0(j): i-invariant
        s_ax0[k] = v.x; s_ax1[k] = __fadd_rn(v.x, v.z);
    } else if (t >= 192) {
        int i = t - 192;
        float4 v = anc4[(a*HH + i)*WW];         // y0(i): j-invariant
        s_ay0[i] = v.y; s_ay1[i] = __fadd_rn(v.y, v.w);
    }
    const float4 A0 = anc4[a*HH*WW];            // w,h constant per a
    const float aw = A0.z, ah = A0.w;
    const float aarea = __fmul_rn(aw, ah);
    __syncthreads();

    // ---- phase 2: separable precompute ----
    if (t < GG) s_u0[t] = __fadd_rn(aarea, s_ga[t]);
#pragma unroll
    for (int k = 0; k < 2; ++k) {               // iw: 512 entries
        int idx = t + k*256;
        int g = idx & 63, jl = idx >> 6;
        const float4 gb = s_gb[g];
        s_iw[jl*64 + g] = fmaxf(0.f, __fsub_rn(fminf(s_ax1[jl], gb.z),
                                               fmaxf(s_ax0[jl], gb.x)));
    }
#pragma unroll
    for (int k = 0; k < 8; ++k) {               // ih2: 2048 float2 entries
        int idx = t + k*256;
        int g = idx >> 5, ll = idx & 31;
        const float4 gb = s_gb[g];
        float v0 = fmaxf(0.f, __fsub_rn(fminf(s_ay1[ll],    gb.w), fmaxf(s_ay0[ll],    gb.y)));
        float v1 = fmaxf(0.f, __fsub_rn(fminf(s_ay1[ll+32], gb.w), fmaxf(s_ay0[ll+32], gb.y)));
        s_ih2[g*32 + ll] = make_float2(v0, v1);
    }
    __syncthreads();

    // ---- compaction: list of g with iw>0 for this warp's column ----
    {
        float iwA = s_iw[w*64 + l];
        float iwB = s_iw[w*64 + 32 + l];
        unsigned b0 = __ballot_sync(0xFFFFFFFFu, iwA > 0.f);
        unsigned b1 = __ballot_sync(0xFFFFFFFFu, iwB > 0.f);
        int cnt0 = __popc(b0);
        if (b0 & (1u << l)) s_lg[w*64 + __popc(b0 & ((1u<<l)-1u))] = (unsigned char)l;
        if (b1 & (1u << l)) s_lg[w*64 + cnt0 + __popc(b1 & ((1u<<l)-1u))] = (unsigned char)(l + 32);
        if (l == 0) {
            s_nl[w] = cnt0 + __popc(b1);
            unsigned nb0 = ~b0, nb1 = ~b1;
            int fz = 64;
            if (nb0)      fz = __ffs(nb0) - 1;
            else if (nb1) fz = 32 + __ffs(nb1) - 1;
            s_fza[w] = fz;
        }
    }
    __syncwarp();

    // ---- main loop over compacted list (ascending g) ----
    const int nl = s_nl[w];
    float best0 = -1.f, bsl0 = -1.f; int bg0 = 0, fz0 = 64;
    float best1 = -1.f, bsl1 = -1.f; int bg1 = 0, fz1 = 64;

    for (int s = 0; s < nl; ++s) {
        const int   g  = (int)s_lg[w*64 + s];
        const float iw = s_iw[w*64 + g];
        const float2 ih = s_ih2[g*32 + l];
        const float u0 = s_u0[g];
        {   // row l
            float inter = __fmul_rn(iw, ih.x);
            if (inter == 0.f) { if (fz0 == 64) fz0 = g; }
            else {
                float uni = __fsub_rn(u0, inter);
                if (__fmaf_rn(-bsl0, uni, inter) >= 0.f) {   // conservative, rare
                    float ov = __fdiv_rn(inter, uni);
                    if (ov == 0.f) ov = 1e-10f;
                    if (ov > best0) {
                        best0 = ov; bg0 = g;
                        bsl0 = __fmul_rn(best0, 0.99999952f); // 1 - 2^-21
                    }
                }
            }
        }
        {   // row l+32
            float inter = __fmul_rn(iw, ih.y);
            if (inter == 0.f) { if (fz1 == 64) fz1 = g; }
            else {
                float uni = __fsub_rn(u0, inter);
                if (__fmaf_rn(-bsl1, uni, inter) >= 0.f) {
                    float ov = __fdiv_rn(inter, uni);
                    if (ov == 0.f) ov = 1e-10f;
                    if (ov > best1) {
                        best1 = ov; bg1 = g;
                        bsl1 = __fmul_rn(best1, 0.99999952f);
                    }
                }
            }
        }
    }
    // merge zero-candidates (value 1e-10 at first zero-inter index)
    {
        int fz = min(s_fza[w], fz0);
        if (fz < 64) {
            if (best0 < 1e-10f)                     { best0 = 1e-10f; bg0 = fz; }
            else if (best0 == 1e-10f && fz < bg0)   bg0 = fz;
        }
        fz = min(s_fza[w], fz1);
        if (fz < 64) {
            if (best1 < 1e-10f)                     { best1 = 1e-10f; bg1 = fz; }
            else if (best1 == 1e-10f && fz < bg1)   bg1 = fz;
        }
    }

    // ---- epilogue ----
    const float L = 63.0f;
    const float x0 = s_ax0[w];
    const bool keep_x = (x0 >= 0.f) && (aw >= 0.f) && (ah >= 0.f) &&
                        (x0 <= L) && (__fsub_rn(s_ax1[w], 1.0f) <= L);
    int myp = 0, myn = 0;

#pragma unroll
    for (int rr = 0; rr < 2; ++rr) {
        const int   i    = rr ? (l + 32) : l;
        const float best = rr ? best1 : best0;
        const int   bg   = rr ? bg1 : bg0;
        const float y0 = s_ay0[i];
        const bool keep = keep_x && (y0 >= 0.f) && (y0 <= L) &&
                          (__fsub_rn(s_ay1[i], 1.0f) <= L);

        float label = -1.0f; bool lab0 = false;
        if (keep) {
            if (best >= 0.7f)       label = 1.0f;
            else if (best <= 0.3f)  lab0 = true;   // tentative -1
            myp += (best > 0.7f);
            myn += (best < 0.3f);
        }

        float* so = s_out + (i*8 + w)*5;
        so[0] = label;
        if (keep) {
            const float4 g0 = s_g0[bg];
            so[1] = __fsub_rn(x0, __fmul_rn(g0.x, 0.0625f));
            so[2] = __fsub_rn(y0, __fmul_rn(g0.y, 0.0625f));
            so[3] = __fsub_rn(aw, __fmul_rn(g0.z, 0.0625f));
            so[4] = __fsub_rn(ah, __fmul_rn(g0.w, 0.0625f));
        } else {
            so[1] = 0.f; so[2] = 0.f; so[3] = 0.f; so[4] = 0.f;
        }

        const int n = (a*HH + i)*WW + (j0 + w);
        unsigned u = SENT;
        if (lab0) {
            u = threefry_bits((unsigned)(b*NN + n)) >> 9;
            int bucket = (int)(u >> 13);
            unsigned slot = atomicAdd(&g_hist[b*NBUCK + bucket], 1u);
            if (slot < SLOTS)
                g_list[((size_t)(b*NBUCK + bucket))*SLOTS + slot] =
                    ((unsigned long long)u << 32) | (unsigned)n;
        }
        s_ub[i*8 + w] = u;
    }

    for (int o = 16; o > 0; o >>= 1) {
        myp += __shfl_down_sync(0xFFFFFFFFu, myp, o);
        myn += __shfl_down_sync(0xFFFFFFFFu, myn, o);
    }
    if (l == 0) {
        if (myp) atomicAdd(&s_p, (unsigned)myp);
        if (myn) atomicAdd(&s_n, (unsigned)myn);
    }
    __syncthreads();
    if (t == 0) {
        if (s_p) atomicAdd(&g_pos, s_p);
        if (s_n) atomicAdd(&g_neg, s_n);
    }

    // ---- staged writes ----
    const float4* so4 = (const float4*)s_out;
    float4* o4 = (float4*)out;
    const size_t obase = (size_t)(b*AA + a) * 5120;   // HH*WW*5/4
#pragma unroll
    for (int k = 0; k < 3; ++k) {
        int f = t + k*256;
        if (f < 640) {
            int i = f / 10, p = f % 10;
            o4[obase + (size_t)i*80 + jt*10 + p] = so4[f];
        }
    }
    if (t < 128) {
        int i = t >> 1, part = t & 1;
        const uint4* su4 = (const uint4*)s_ub;
        uint4* u4 = (uint4*)g_ubuf;
        u4[((size_t)b*NN + a*HH*WW)/4 + (size_t)i*16 + jt*2 + part] = su4[t];
    }
}

// ---------------- kernel 2: fused scan + restore + state-clean --------------
// 16 blocks (one per row) x 1024 threads. Hierarchical SHUFFLE scan (2 block
// barriers instead of 20): warp-level inclusive scan, warp totals scanned by
// warp 0, offsets added back. Rest identical to R14.
__global__ void __launch_bounds__(1024) finish_kernel(float* __restrict__ out) {
    const int b = blockIdx.x;
    const int t = threadIdx.x;
    const int wid = t >> 5, lane = t & 31;

    __shared__ unsigned sh_cnt[NBUCK];   // counts by bucket
    __shared__ unsigned sh_w[32], sh_o[32];
    __shared__ unsigned s_pn[2];
    __shared__ int s_T, s_ovf;
    __shared__ unsigned s_S;
    __shared__ unsigned s_u[SLOTS], s_i[SLOTS];

    if (t == 0) {
        s_pn[0] = g_pos; s_pn[1] = g_neg;   // loads complete before the
        s_T = -1; s_ovf = 0;                 // dependent shared stores do
    }
    unsigned* hrow = g_hist + b*NBUCK;
    const unsigned cnt = hrow[t];            // own bucket t
    sh_cnt[t] = cnt;
    __syncthreads();                         // pos/neg + counts staged
    hrow[t] = 0u;                            // self-clean for next replay
    if (t == 0) {
        unsigned old = atomicInc(&g_done, 15u);   // wraps 15 -> 0
        if (old == 15u) { g_pos = 0u; g_neg = 0u; }  // all 16 blocks have read
    }

    const unsigned pos = s_pn[0], negc = s_pn[1];
    const unsigned cutoff = (unsigned)max(1, 3 * (int)pos);
    const unsigned* row = g_ubuf + (size_t)b*NN;

    if (negc <= cutoff) {
        // no disable: restore ALL label-0 (u != SENT)
        const uint4* r4 = (const uint4*)row;
#pragma unroll
        for (int k = 0; k < 12; ++k) {       // 12288 uint4 / 1024 threads
            int f = t + k*1024;
            uint4 u4 = r4[f];
            int j = f*4;
            if (u4.x != SENT) out[((size_t)b*NN + j+0)*5] = 0.0f;
            if (u4.y != SENT) out[((size_t)b*NN + j+1)*5] = 0.0f;
            if (u4.z != SENT) out[((size_t)b*NN + j+2)*5] = 0.0f;
            if (u4.w != SENT) out[((size_t)b*NN + j+3)*5] = 0.0f;
        }
        return;
    }

    // ---- hierarchical scan over descending buckets (thread t -> hi=1023-t) --
    const int hi = (NBUCK - 1) - t;
    const unsigned v = sh_cnt[hi];
    unsigned incl = v;
#pragma unroll
    for (int o = 1; o < 32; o <<= 1) {
        unsigned tv = __shfl_up_sync(0xFFFFFFFFu, incl, o);
        if (lane >= o) incl += tv;
    }
    if (lane == 31) sh_w[wid] = incl;
    __syncthreads();
    if (wid == 0) {
        unsigned wv = sh_w[lane];
        unsigned wincl = wv;
#pragma unroll
        for (int o = 1; o < 32; o <<= 1) {
            unsigned tv = __shfl_up_sync(0xFFFFFFFFu, wincl, o);
            if (lane >= o) wincl += tv;
        }
        sh_o[lane] = wincl - wv;             // exclusive warp offset
    }
    __syncthreads();
    incl += sh_o[wid];
    const unsigned excl = incl - v;
    if (excl < cutoff && incl >= cutoff) { s_T = hi; s_S = excl; }  // unique
    if (v > SLOTS) s_ovf = 1;                // conservative (any bucket)
    __syncthreads();
    const int T = s_T;
    const unsigned S = s_S;
    // T always found: sum(hist) = #label0 >= negc > cutoff.

    if (!s_ovf) {
        // warp-strided buckets above T; counts from shared (no global chain)
        for (int q = T + 1 + wid; q < NBUCK; q += 32) {
            const unsigned c = sh_cnt[q];
            const unsigned long long* lst = g_list + ((size_t)(b*NBUCK + q))*SLOTS;
            for (unsigned e = lane; e < c; e += 32) {
                unsigned idx = (unsigned)(lst[e] & 0xFFFFFFFFu);
                out[((size_t)b*NN + idx)*5] = 0.0f;
            }
        }
        // boundary bucket T: exact rank (cT <= SLOTS since no overflow)
        const unsigned cT = sh_cnt[T];
        const unsigned long long* lst = g_list + ((size_t)(b*NBUCK + T))*SLOTS;
        if (t < cT) {
            unsigned long long p = lst[t];
            s_u[t] = (unsigned)(p >> 32);
            s_i[t] = (unsigned)(p & 0xFFFFFFFFu);
        }
        __syncthreads();
        if (t < cT) {
            unsigned ua = s_u[t], ia = s_i[t];
            unsigned c2 = S;
            for (unsigned k = 0; k < cT; ++k) {
                unsigned ub = s_u[k];
                if (ub > ua || (ub == ua && s_i[k] < ia)) c2++;
            }
            if (c2 < cutoff) out[((size_t)b*NN + ia)*5] = 0.0f;   // kept
        }
    } else {
        // overflow fallback: full-row scan via g_ubuf
        for (int j = t; j < NN; j += 1024) {
            unsigned u = row[j];
            if (u != SENT && (int)(u >> 13) > T)
                out[((size_t)b*NN + j)*5] = 0.0f;
        }
        for (int a = t; a < NN; a += 1024) {
            unsigned ua = row[a];
            if (ua == SENT || (int)(ua >> 13) != T) continue;
            unsigned c2 = S;
            for (int jx = 0; jx < NN; ++jx) {
                unsigned uj = row[jx];
                if (uj != SENT && (int)(uj >> 13) == T &&
                    (uj > ua || (uj == ua && jx < a))) c2++;
            }
            if (c2 < cutoff) out[((size_t)b*NN + a)*5] = 0.0f;
        }
    }
}

// ---------------- launch ----------------------------------------------------
extern "C" void kernel_launch(void* const* d_in, const int* in_sizes, int n_in,
                              void* d_out, int out_size) {
    const float* gt      = (const float*)d_in[1];
    const float* anchors = (const float*)d_in[2];
    for (int k = 0; k < n_in; ++k) {
        if (in_sizes[k] == BB*GG*4) gt      = (const float*)d_in[k];
        if (in_sizes[k] == NN*4)    anchors = (const float*)d_in[k];
    }
    float* out = (float*)d_out;

    dim3 mgrid(8, AA, BB);                 // 8 j-tiles x 12 a x 16 b = 1536
    main_kernel<<<mgrid, 256>>>(gt, anchors, out);
    finish_kernel<<<BB, 1024>>>(out);
}

// round 17
// speedup vs baseline: 1.1079x; 1.0608x over previous
#include <cuda_runtime.h>
#include <stdint.h>

#define BB 16
#define AA 12
#define HH 64
#define WW 64
#define GG 64
#define NN (AA*HH*WW)        /* 49152 anchors per batch */
#define TOT (BB*NN)          /* 786432 */
#define NBUCK 1024
#define SENT 0xFFFFFFFFu
#define SLOTS 128
#define RSPLIT 8             /* finish blocks per row */

// ---------------- scratch (static __device__, no allocation) ----------------
// INVARIANT: g_hist, g_pos, g_neg, g_done, g_rdone are zero at every
// kernel_launch entry (zero at module load; finish_kernel self-cleans each
// call; counters self-wrap via atomicInc). g_list/g_ubuf fully overwritten.
__device__ unsigned g_ubuf[TOT];                       // fallback store of u
__device__ unsigned g_hist[BB*NBUCK];                  // counts (u>>13)
__device__ unsigned long long g_list[(size_t)BB*NBUCK*SLOTS]; // (u<<32)|idx
__device__ unsigned g_pos, g_neg;
__device__ unsigned g_done;                            // wraps 0..127
__device__ unsigned g_rdone[BB];                       // wrap 0..7 per row

// ------- Threefry-2x32-20, key=(0,42), PARTITIONABLE layout -----------------
__device__ __forceinline__ unsigned threefry_bits(unsigned i) {
    unsigned x0 = 0u, x1 = i;
    const unsigned k0 = 0u, k1 = 42u, k2 = 0x1BD11BDAu ^ 0u ^ 42u;
    x0 += k0; x1 += k1;
#define TFR(r) { x0 += x1; x1 = __funnelshift_l(x1, x1, (r)); x1 ^= x0; }
    TFR(13) TFR(15) TFR(26) TFR(6)   x0 += k1; x1 += k2 + 1u;
    TFR(17) TFR(29) TFR(16) TFR(24)  x0 += k2; x1 += k0 + 2u;
    TFR(13) TFR(15) TFR(26) TFR(6)   x0 += k0; x1 += k1 + 3u;
    TFR(17) TFR(29) TFR(16) TFR(24)  x0 += k1; x1 += k2 + 4u;
    TFR(13) TFR(15) TFR(26) TFR(6)   x0 += k2; x1 += k0 + 5u;
#undef TFR
    return x0 ^ x1;
}

// ---------------- kernel 1: IoU / labels / targets / PRNG / lists -----------
// (identical to R12/R14/R16 best) Block = (jt, a, b): 64 rows x 8 columns;
// warp w owns column j = jt*8 + w; lane l owns rows l and l+32. Separable IoU
// + compacted g-list; division-free guard with exact __fdiv_rn fallback =>
// bit-identical. Label-0 written as -1 tentatively; finish restores kept ones.
__global__ void __launch_bounds__(256) main_kernel(
        const float* __restrict__ gt,       // (B,G,4)
        const float* __restrict__ anchors,  // (N,4)
        float* __restrict__ out)            // (B,N,5)
{
    __shared__ float4 s_gb[GG];          // (gx0, gy0, gx1, gy1)
    __shared__ float4 s_g0[GG];          // raw batch-0 gt boxes (targets quirk)
    __shared__ float  s_ga[GG];
    __shared__ float  s_u0[GG];          // aarea + ga
    __shared__ float  s_ax0[8], s_ax1[8];
    __shared__ float  s_ay0[HH], s_ay1[HH];
    __shared__ float  s_iw[8*GG];        // [jl][g]
    __shared__ float2 s_ih2[GG*32];      // [g][l] -> (ih row l, ih row l+32)
    __shared__ unsigned char s_lg[8*GG]; // compacted g indices per column
    __shared__ int    s_nl[8], s_fza[8]; // list length, first iw==0 g
    __shared__ float  s_out[HH*8*5];     // staged output (2560 floats)
    __shared__ unsigned s_ub[HH*8];      // staged u
    __shared__ unsigned s_p, s_n;

    const int b  = blockIdx.z;
    const int a  = blockIdx.y;
    const int jt = blockIdx.x;
    const int j0 = jt * 8;
    const int t  = threadIdx.x;
    const int w  = t >> 5;               // local column
    const int l  = t & 31;

    const float4* anc4 = (const float4*)anchors;

    // ---- phase 1: stage ----
    if (t == 0) { s_p = 0u; s_n = 0u; }
    if (t < GG) {
        const float4 gp = *(const float4*)(gt + ((size_t)b*GG + t)*4);
        s_gb[t] = make_float4(gp.x, gp.y,
                              __fadd_rn(gp.x, gp.z), __fadd_rn(gp.y, gp.w));
        s_ga[t] = __fmul_rn(gp.z, gp.w);
    } else if (t < 2*GG) {
        s_g0[t - GG] = *(const float4*)(gt + (size_t)(t - GG)*4);   // batch 0
    } else if (t < 136) {
        int k = t - 128;
        float4 v = anc4[a*HH*WW + j0 + k];      // x0(j): i-invariant
        s_ax0[k] = v.x; s_ax1[k] = __fadd_rn(v.x, v.z);
    } else if (t >= 192) {
        int i = t - 192;
        float4 v = anc4[(a*HH + i)*WW];         // y0(i): j-invariant
        s_ay0[i] = v.y; s_ay1[i] = __fadd_rn(v.y, v.w);
    }
    const float4 A0 = anc4[a*HH*WW];            // w,h constant per a
    const float aw = A0.z, ah = A0.w;
    const float aarea = __fmul_rn(aw, ah);
    __syncthreads();

    // ---- phase 2: separable precompute ----
    if (t < GG) s_u0[t] = __fadd_rn(aarea, s_ga[t]);
#pragma unroll
    for (int k = 0; k < 2; ++k) {               // iw: 512 entries
        int idx = t + k*256;
        int g = idx & 63, jl = idx >> 6;
        const float4 gb = s_gb[g];
        s_iw[jl*64 + g] = fmaxf(0.f, __fsub_rn(fminf(s_ax1[jl], gb.z),
                                               fmaxf(s_ax0[jl], gb.x)));
    }
#pragma unroll
    for (int k = 0; k < 8; ++k) {               // ih2: 2048 float2 entries
        int idx = t + k*256;
        int g = idx >> 5, ll = idx & 31;
        const float4 gb = s_gb[g];
        float v0 = fmaxf(0.f, __fsub_rn(fminf(s_ay1[ll],    gb.w), fmaxf(s_ay0[ll],    gb.y)));
        float v1 = fmaxf(0.f, __fsub_rn(fminf(s_ay1[ll+32], gb.w), fmaxf(s_ay0[ll+32], gb.y)));
        s_ih2[g*32 + ll] = make_float2(v0, v1);
    }
    __syncthreads();

    // ---- compaction: list of g with iw>0 for this warp's column ----
    {
        float iwA = s_iw[w*64 + l];
        float iwB = s_iw[w*64 + 32 + l];
        unsigned b0 = __ballot_sync(0xFFFFFFFFu, iwA > 0.f);
        unsigned b1 = __ballot_sync(0xFFFFFFFFu, iwB > 0.f);
        int cnt0 = __popc(b0);
        if (b0 & (1u << l)) s_lg[w*64 + __popc(b0 & ((1u<<l)-1u))] = (unsigned char)l;
        if (b1 & (1u << l)) s_lg[w*64 + cnt0 + __popc(b1 & ((1u<<l)-1u))] = (unsigned char)(l + 32);
        if (l == 0) {
            s_nl[w] = cnt0 + __popc(b1);
            unsigned nb0 = ~b0, nb1 = ~b1;
            int fz = 64;
            if (nb0)      fz = __ffs(nb0) - 1;
            else if (nb1) fz = 32 + __ffs(nb1) - 1;
            s_fza[w] = fz;
        }
    }
    __syncwarp();

    // ---- main loop over compacted list (ascending g) ----
    const int nl = s_nl[w];
    float best0 = -1.f, bsl0 = -1.f; int bg0 = 0, fz0 = 64;
    float best1 = -1.f, bsl1 = -1.f; int bg1 = 0, fz1 = 64;

    for (int s = 0; s < nl; ++s) {
        const int   g  = (int)s_lg[w*64 + s];
        const float iw = s_iw[w*64 + g];
        const float2 ih = s_ih2[g*32 + l];
        const float u0 = s_u0[g];
        {   // row l
            float inter = __fmul_rn(iw, ih.x);
            if (inter == 0.f) { if (fz0 == 64) fz0 = g; }
            else {
                float uni = __fsub_rn(u0, inter);
                if (__fmaf_rn(-bsl0, uni, inter) >= 0.f) {   // conservative, rare
                    float ov = __fdiv_rn(inter, uni);
                    if (ov == 0.f) ov = 1e-10f;
                    if (ov > best0) {
                        best0 = ov; bg0 = g;
                        bsl0 = __fmul_rn(best0, 0.99999952f); // 1 - 2^-21
                    }
                }
            }
        }
        {   // row l+32
            float inter = __fmul_rn(iw, ih.y);
            if (inter == 0.f) { if (fz1 == 64) fz1 = g; }
            else {
                float uni = __fsub_rn(u0, inter);
                if (__fmaf_rn(-bsl1, uni, inter) >= 0.f) {
                    float ov = __fdiv_rn(inter, uni);
                    if (ov == 0.f) ov = 1e-10f;
                    if (ov > best1) {
                        best1 = ov; bg1 = g;
                        bsl1 = __fmul_rn(best1, 0.99999952f);
                    }
                }
            }
        }
    }
    // merge zero-candidates (value 1e-10 at first zero-inter index)
    {
        int fz = min(s_fza[w], fz0);
        if (fz < 64) {
            if (best0 < 1e-10f)                     { best0 = 1e-10f; bg0 = fz; }
            else if (best0 == 1e-10f && fz < bg0)   bg0 = fz;
        }
        fz = min(s_fza[w], fz1);
        if (fz < 64) {
            if (best1 < 1e-10f)                     { best1 = 1e-10f; bg1 = fz; }
            else if (best1 == 1e-10f && fz < bg1)   bg1 = fz;
        }
    }

    // ---- epilogue ----
    const float L = 63.0f;
    const float x0 = s_ax0[w];
    const bool keep_x = (x0 >= 0.f) && (aw >= 0.f) && (ah >= 0.f) &&
                        (x0 <= L) && (__fsub_rn(s_ax1[w], 1.0f) <= L);
    int myp = 0, myn = 0;

#pragma unroll
    for (int rr = 0; rr < 2; ++rr) {
        const int   i    = rr ? (l + 32) : l;
        const float best = rr ? best1 : best0;
        const int   bg   = rr ? bg1 : bg0;
        const float y0 = s_ay0[i];
        const bool keep = keep_x && (y0 >= 0.f) && (y0 <= L) &&
                          (__fsub_rn(s_ay1[i], 1.0f) <= L);

        float label = -1.0f; bool lab0 = false;
        if (keep) {
            if (best >= 0.7f)       label = 1.0f;
            else if (best <= 0.3f)  lab0 = true;   // tentative -1
            myp += (best > 0.7f);
            myn += (best < 0.3f);
        }

        float* so = s_out + (i*8 + w)*5;
        so[0] = label;
        if (keep) {
            const float4 g0 = s_g0[bg];
            so[1] = __fsub_rn(x0, __fmul_rn(g0.x, 0.0625f));
            so[2] = __fsub_rn(y0, __fmul_rn(g0.y, 0.0625f));
            so[3] = __fsub_rn(aw, __fmul_rn(g0.z, 0.0625f));
            so[4] = __fsub_rn(ah, __fmul_rn(g0.w, 0.0625f));
        } else {
            so[1] = 0.f; so[2] = 0.f; so[3] = 0.f; so[4] = 0.f;
        }

        const int n = (a*HH + i)*WW + (j0 + w);
        unsigned u = SENT;
        if (lab0) {
            u = threefry_bits((unsigned)(b*NN + n)) >> 9;
            int bucket = (int)(u >> 13);
            unsigned slot = atomicAdd(&g_hist[b*NBUCK + bucket], 1u);
            if (slot < SLOTS)
                g_list[((size_t)(b*NBUCK + bucket))*SLOTS + slot] =
                    ((unsigned long long)u << 32) | (unsigned)n;
        }
        s_ub[i*8 + w] = u;
    }

    for (int o = 16; o > 0; o >>= 1) {
        myp += __shfl_down_sync(0xFFFFFFFFu, myp, o);
        myn += __shfl_down_sync(0xFFFFFFFFu, myn, o);
    }
    if (l == 0) {
        if (myp) atomicAdd(&s_p, (unsigned)myp);
        if (myn) atomicAdd(&s_n, (unsigned)myn);
    }
    __syncthreads();
    if (t == 0) {
        if (s_p) atomicAdd(&g_pos, s_p);
        if (s_n) atomicAdd(&g_neg, s_n);
    }

    // ---- staged writes ----
    const float4* so4 = (const float4*)s_out;
    float4* o4 = (float4*)out;
    const size_t obase = (size_t)(b*AA + a) * 5120;   // HH*WW*5/4
#pragma unroll
    for (int k = 0; k < 3; ++k) {
        int f = t + k*256;
        if (f < 640) {
            int i = f / 10, p = f % 10;
            o4[obase + (size_t)i*80 + jt*10 + p] = so4[f];
        }
    }
    if (t < 128) {
        int i = t >> 1, part = t & 1;
        const uint4* su4 = (const uint4*)s_ub;
        uint4* u4 = (uint4*)g_ubuf;
        u4[((size_t)b*NN + a*HH*WW)/4 + (size_t)i*16 + jt*2 + part] = su4[t];
    }
}

// ---------------- kernel 2: fused scan + restore + state-clean --------------
// Grid (RSPLIT=8, BB) x 1024 threads: 8 blocks per row. Each block stages the
// row's 1024-bucket hist to shared (4KB, redundant but cheap), shuffle-scans
// it, then restores its 1/8 of buckets above T (256 warps/row total). Hist is
// zeroed by the LAST of the 8 row-blocks (per-row wrap counter; the barrier
// after staging guarantees all its loads completed). pos/neg zeroed by the
// 128th block overall. Block x==0 fine-ranks boundary bucket T / handles the
// overflow fallback; restore_all split 8 ways.
__global__ void __launch_bounds__(1024) finish_kernel(float* __restrict__ out) {
    const int bx = blockIdx.x;
    const int b  = blockIdx.y;
    const int t  = threadIdx.x;
    const int wid = t >> 5, lane = t & 31;

    __shared__ unsigned sh_cnt[NBUCK];   // counts by bucket
    __shared__ unsigned sh_w[32], sh_o[32];
    __shared__ unsigned s_pn[2];
    __shared__ int s_T, s_ovf, s_last;
    __shared__ unsigned s_S;
    __shared__ unsigned s_u[SLOTS], s_i[SLOTS];

    if (t == 0) {
        s_pn[0] = g_pos; s_pn[1] = g_neg;   // loads complete before the
        s_T = -1; s_ovf = 0;                 // dependent shared stores do
    }
    unsigned* hrow = g_hist + b*NBUCK;
    sh_cnt[t] = hrow[t];                     // own bucket t
    __syncthreads();                         // all loads of this block done
    if (t == 0) {
        s_last = (atomicInc(&g_rdone[b], (unsigned)(RSPLIT-1)) ==
                  (unsigned)(RSPLIT-1));     // wraps 7 -> 0
        unsigned old = atomicInc(&g_done, 127u);       // wraps 127 -> 0
        if (old == 127u) { g_pos = 0u; g_neg = 0u; }   // all blocks have read
    }
    __syncthreads();
    if (s_last) hrow[t] = 0u;                // self-clean, after all 8 reads

    const unsigned pos = s_pn[0], negc = s_pn[1];
    const unsigned cutoff = (unsigned)max(1, 3 * (int)pos);
    const unsigned* row = g_ubuf + (size_t)b*NN;

    if (negc <= cutoff) {
        // no disable: restore ALL label-0 (u != SENT); split across 8 blocks
        const uint4* r4 = (const uint4*)row;
#pragma unroll
        for (int k = 0; k < 2; ++k) {        // 12288/8 = 1536 uint4 per block
            int fl = t + k*1024;
            if (fl < 1536) {
                int f = bx*1536 + fl;
                uint4 u4 = r4[f];
                int j = f*4;
                if (u4.x != SENT) out[((size_t)b*NN + j+0)*5] = 0.0f;
                if (u4.y != SENT) out[((size_t)b*NN + j+1)*5] = 0.0f;
                if (u4.z != SENT) out[((size_t)b*NN + j+2)*5] = 0.0f;
                if (u4.w != SENT) out[((size_t)b*NN + j+3)*5] = 0.0f;
            }
        }
        return;
    }

    // ---- hierarchical shuffle scan over descending buckets (hi = 1023-t) ----
    const int hi = (NBUCK - 1) - t;
    const unsigned v = sh_cnt[hi];
    unsigned incl = v;
#pragma unroll
    for (int o = 1; o < 32; o <<= 1) {
        unsigned tv = __shfl_up_sync(0xFFFFFFFFu, incl, o);
        if (lane >= o) incl += tv;
    }
    if (lane == 31) sh_w[wid] = incl;
    __syncthreads();
    if (wid == 0) {
        unsigned wv = sh_w[lane];
        unsigned wincl = wv;
#pragma unroll
        for (int o = 1; o < 32; o <<= 1) {
            unsigned tv = __shfl_up_sync(0xFFFFFFFFu, wincl, o);
            if (lane >= o) wincl += tv;
        }
        sh_o[lane] = wincl - wv;             // exclusive warp offset
    }
    __syncthreads();
    incl += sh_o[wid];
    const unsigned excl = incl - v;
    if (excl < cutoff && incl >= cutoff) { s_T = hi; s_S = excl; }  // unique
    if (v > SLOTS) s_ovf = 1;                // conservative (any bucket)
    __syncthreads();
    const int T = s_T;
    const unsigned S = s_S;
    // T always found: sum(hist) = #label0 >= negc > cutoff.

    if (!s_ovf) {
        // 256 warps/row strided over buckets above T; counts from shared
        const int gw = bx*32 + wid;          // 0..255
        for (int q = T + 1 + gw; q < NBUCK; q += RSPLIT*32) {
            const unsigned c = sh_cnt[q];
            const unsigned long long* lst = g_list + ((size_t)(b*NBUCK + q))*SLOTS;
            for (unsigned e = lane; e < c; e += 32) {
                unsigned idx = (unsigned)(lst[e] & 0xFFFFFFFFu);
                out[((size_t)b*NN + idx)*5] = 0.0f;
            }
        }
        if (bx != 0) return;
        // boundary bucket T: exact rank (cT <= SLOTS since no overflow)
        const unsigned cT = sh_cnt[T];
        const unsigned long long* lst = g_list + ((size_t)(b*NBUCK + T))*SLOTS;
        if (t < cT) {
            unsigned long long p = lst[t];
            s_u[t] = (unsigned)(p >> 32);
            s_i[t] = (unsigned)(p & 0xFFFFFFFFu);
        }
        __syncthreads();
        if (t < cT) {
            unsigned ua = s_u[t], ia = s_i[t];
            unsigned c2 = S;
            for (unsigned k = 0; k < cT; ++k) {
                unsigned ub = s_u[k];
                if (ub > ua || (ub == ua && s_i[k] < ia)) c2++;
            }
            if (c2 < cutoff) out[((size_t)b*NN + ia)*5] = 0.0f;   // kept
        }
    } else {
        if (bx != 0) return;
        // overflow fallback: full-row scan via g_ubuf
        for (int j = t; j < NN; j += 1024) {
            unsigned u = row[j];
            if (u != SENT && (int)(u >> 13) > T)
                out[((size_t)b*NN + j)*5] = 0.0f;
        }
        for (int a = t; a < NN; a += 1024) {
            unsigned ua = row[a];
            if (ua == SENT || (int)(ua >> 13) != T) continue;
            unsigned c2 = S;
            for (int jx = 0; jx < NN; ++jx) {
                unsigned uj = row[jx];
                if (uj != SENT && (int)(uj >> 13) == T &&
                    (uj > ua || (uj == ua && jx < a))) c2++;
            }
            if (c2 < cutoff) out[((size_t)b*NN + a)*5] = 0.0f;
        }
    }
}

// ---------------- launch ----------------------------------------------------
extern "C" void kernel_launch(void* const* d_in, const int* in_sizes, int n_in,
                              void* d_out, int out_size) {
    const float* gt      = (const float*)d_in[1];
    const float* anchors = (const float*)d_in[2];
    for (int k = 0; k < n_in; ++k) {
        if (in_sizes[k] == BB*GG*4) gt      = (const float*)d_in[k];
        if (in_sizes[k] == NN*4)    anchors = (const float*)d_in[k];
    }
    float* out = (float*)d_out;

    dim3 mgrid(8, AA, BB);                 // 8 j-tiles x 12 a x 16 b = 1536
    main_kernel<<<mgrid, 256>>>(gt, anchors, out);
    dim3 fgrid(RSPLIT, BB);                // 8 x 16 = 128 blocks
    finish_kernel<<<fgrid, 1024>>>(out);
}